// round 12
// baseline (speedup 1.0000x reference)
#include <cuda_runtime.h>
#include <cuda_fp16.h>

// Problem constants (fixed shapes for this problem)
#define N_NODES 20000
#define F_IN    8
#define T_P     12
#define HID     32
#define FEAT    96      // F_IN * T_P values per node
#define FEAT4   24      // FEAT / 4
#define NPW     4       // nodes per warp in k_node

// ---------------- device scratch (no allocations allowed) ----------------
// g_cnt starts zero (BSS) and is re-zeroed by k_node at the end of every run,
// so the pipeline is self-restoring across graph replays (no memset node).
__device__ float  g_cnt [N_NODES];               // edge in-degree
__device__ float  g_dinv[N_NODES];               // rsqrt(cnt + 1)
__device__ __align__(16) __half g_aggh[N_NODES * FEAT];  // fp16 accumulator
__device__ __align__(16) __half g_xh  [N_NODES * FEAT];  // fp16(dinv_n * x_n)
__device__ float  g_WLz [F_IN * HID];            // Wz @ Lz_top  (8 x 32)
__device__ float  g_WLh [F_IN * HID];            // Wh @ Lh_top  (8 x 32)
__device__ float  g_blz [HID];                   // bz @ Lz_top + lz
__device__ float  g_blh [HID];                   // bh @ Lh_top + lh
__device__ float  g_probs[T_P];                  // softmax(att)

__device__ __forceinline__ float fast_tanh(float x) {
    float y;
    asm("tanh.approx.f32 %0, %1;" : "=f"(y) : "f"(x));
    return y;
}

// ---- PDL (programmatic dependent launch) controls, sm_90+ ----
__device__ __forceinline__ void pdl_wait() {
    asm volatile("griddepcontrol.wait;" ::: "memory");
}
__device__ __forceinline__ void pdl_launch_dependents() {
    asm volatile("griddepcontrol.launch_dependents;" ::: "memory");
}

// ---- packed f32x2 helpers (Blackwell; exact fp32, 1 instr = 2 FMAs) ----
__device__ __forceinline__ unsigned long long pack2(float a, float b) {
    unsigned long long r;
    asm("mov.b64 %0, {%1, %2};" : "=l"(r) : "f"(a), "f"(b));
    return r;
}
__device__ __forceinline__ void unpack2(unsigned long long v, float& a, float& b) {
    asm("mov.b64 {%0, %1}, %2;" : "=f"(a), "=f"(b) : "l"(v));
}
__device__ __forceinline__ unsigned long long fma2(unsigned long long a,
                                                   unsigned long long b,
                                                   unsigned long long c) {
    unsigned long long r;
    asm("fma.rn.f32x2 %0, %1, %2, %3;" : "=l"(r) : "l"(a), "l"(b), "l"(c));
    return r;
}
__device__ __forceinline__ unsigned long long mul2(unsigned long long a,
                                                   unsigned long long b) {
    unsigned long long r;
    asm("mul.rn.f32x2 %0, %1, %2;" : "=l"(r) : "l"(a), "l"(b));
    return r;
}

// ---------------- kernels ----------------

// Degree histogram (4 edges/thread). Block 0 additionally folds the gate
// weights (WL = W @ L_top, bl = b @ L_top + l) and computes softmax(att).
__global__ void k_count_pre(const int4* __restrict__ dst4, int E4,
                            const float* __restrict__ Wz, const float* __restrict__ bz,
                            const float* __restrict__ Wh, const float* __restrict__ bh,
                            const float* __restrict__ Lz, const float* __restrict__ lz,
                            const float* __restrict__ Lh, const float* __restrict__ lh,
                            const float* __restrict__ att) {
    int i = blockIdx.x * blockDim.x + threadIdx.x;
    if (i < E4) {
        int4 d = __ldg(&dst4[i]);
        atomicAdd(&g_cnt[d.x], 1.0f);
        atomicAdd(&g_cnt[d.y], 1.0f);
        atomicAdd(&g_cnt[d.z], 1.0f);
        atomicAdd(&g_cnt[d.w], 1.0f);
    }
    if (blockIdx.x == 0) {
        int tid = threadIdx.x;
        if (tid < F_IN * HID) {
            int f = tid >> 5, h = tid & 31;
            float az = 0.f, ah = 0.f;
            #pragma unroll 8
            for (int k = 0; k < HID; k++) {
                az = fmaf(Wz[f * HID + k], Lz[k * HID + h], az);
                ah = fmaf(Wh[f * HID + k], Lh[k * HID + h], ah);
            }
            g_WLz[tid] = az;
            g_WLh[tid] = ah;
        }
        if (tid < HID) {
            float az = lz[tid], ah = lh[tid];
            for (int k = 0; k < HID; k++) {
                az = fmaf(bz[k], Lz[k * HID + tid], az);
                ah = fmaf(bh[k], Lh[k * HID + tid], ah);
            }
            g_blz[tid] = az;
            g_blh[tid] = ah;
        }
        if (tid == 0) {
            float m = -1e30f;
            for (int t = 0; t < T_P; t++) m = fmaxf(m, att[t]);
            float e[T_P], s = 0.f;
            for (int t = 0; t < T_P; t++) { e[t] = __expf(att[t] - m); s += e[t]; }
            float inv = 1.0f / s;
            for (int t = 0; t < T_P; t++) g_probs[t] = e[t] * inv;
        }
    }
    pdl_launch_dependents();                      // all of this block's writes done
}

// Node-indexed mid pass: dinv, fp16 pre-scaled features (xh), and seed the
// fp16 accumulator with the self-loop term. One thread per 4-value chunk.
__global__ void k_mid(const float4* __restrict__ x4) {
    pdl_wait();                                   // g_cnt must be complete
    int i = blockIdx.x * blockDim.x + threadIdx.x;
    if (i < N_NODES * FEAT4) {
        int n = i / FEAT4;
        float dn = rsqrtf(__ldg(&g_cnt[n]) + 1.0f);
        if ((i - n * FEAT4) == 0) g_dinv[n] = dn;
        float4 v = __ldg(&x4[i]);
        uint2 hv;
        *(__half2*)&hv.x = __floats2half2_rn(dn * v.x, dn * v.y);
        *(__half2*)&hv.y = __floats2half2_rn(dn * v.z, dn * v.w);
        ((uint2*)g_xh)[i]   = hv;
        ((uint2*)g_aggh)[i] = hv;                 // self-loop seed
    }
    pdl_launch_dependents();
}

// Scatter: aggh[dst] += xh[src]  (both fp16; vector f16x2 reductions).
// 4 threads per edge; lane owns 16B chunks sub, sub+4, sub+8.
__global__ void k_scatter(const int* __restrict__ src,
                          const int* __restrict__ dst, int E) {
    pdl_wait();                                   // xh/aggh seed must be complete
    int i = blockIdx.x * blockDim.x + threadIdx.x;
    int e = i >> 2;
    if (e < E) {
        int sub = i & 3;
        int s = __ldg(&src[e]);
        int d = __ldg(&dst[e]);

        const uint4* xs = (const uint4*)g_xh + s * 12;   // 12 x 16B = 96 halves
        uint4* ad = (uint4*)g_aggh + d * 12;
        #pragma unroll
        for (int k = 0; k < 3; k++) {
            int c = sub + k * 4;                  // 16B-chunk index 0..11
            uint4 v = __ldg(&xs[c]);
            asm volatile("red.global.add.noftz.v4.f16x2 [%0], {%1, %2, %3, %4};"
                         :: "l"(&ad[c]), "r"(v.x), "r"(v.y), "r"(v.z), "r"(v.w)
                         : "memory");
        }
    }
    pdl_launch_dependents();
}

// One warp handles NPW consecutive nodes; weights packed once per warp,
// depth-1 prefetch of the next node's fp16 agg, double-buffered smem.
// Also re-zeroes g_cnt for the next graph replay.
__global__ void __launch_bounds__(256, 4)
k_node(const float* __restrict__ Wout,
       const float* __restrict__ bout,
       float* __restrict__ out) {
    __shared__ __align__(16) float sh[8][2][FEAT];   // per-warp double buffer
    __shared__ float sWout[HID * T_P];
    __shared__ float sBout[T_P];
    __shared__ float sProbs[T_P];

    const int tid  = threadIdx.x;
    const int w    = tid >> 5;
    const int lane = tid & 31;

    pdl_wait();                                   // aggh reductions complete

    // Reset the degree histogram for the next replay (self-restoring graph).
    {
        int gi = blockIdx.x * 256 + tid;
        if (gi < N_NODES) g_cnt[gi] = 0.0f;
    }

    for (int i = tid; i < HID * T_P; i += 256) sWout[i] = Wout[i];
    if (tid < T_P) { sBout[tid] = bout[tid]; sProbs[tid] = g_probs[tid]; }
    __syncthreads();

    // Packed gate weights (lane == hidden index h), duplicated into f32x2.
    unsigned long long wzd[F_IN], whd[F_IN];
    #pragma unroll
    for (int f = 0; f < F_IN; f++) {
        float a = __ldg(&g_WLz[f * HID + lane]);
        float b = __ldg(&g_WLh[f * HID + lane]);
        wzd[f] = pack2(a, a);
        whd[f] = pack2(b, b);
    }
    const float bz0 = __ldg(&g_blz[lane]);
    const float bh0 = __ldg(&g_blh[lane]);
    const unsigned long long bzd_ = pack2(bz0, bz0);
    const unsigned long long bhd_ = pack2(bh0, bh0);
    const unsigned long long hfd_ = pack2(0.5f, 0.5f);

    const int gwarp = blockIdx.x * 8 + w;
    const int base  = gwarp * NPW;
    const uint2* aggh2 = (const uint2*)g_aggh;    // 24 x 8B chunks per node

    // Prefetch node base (lane<24: one 8B chunk = 4 halves).
    uint2 A = make_uint2(0u, 0u);
    float dn = 0.f;
    if (base < N_NODES) {
        if (lane < FEAT4) A = __ldg(&aggh2[base * FEAT4 + lane]);
        dn = __ldg(&g_dinv[base]);
    }

    #pragma unroll
    for (int j = 0; j < NPW; j++) {
        const int n = base + j;
        if (n >= N_NODES) break;
        const int buf = j & 1;

        // Convert + scale current to smem; then prefetch next node.
        if (lane < FEAT4) {
            float2 a = __half22float2(*(const __half2*)&A.x);
            float2 b = __half22float2(*(const __half2*)&A.y);
            float4 B;
            B.x = dn * a.x; B.y = dn * a.y; B.z = dn * b.x; B.w = dn * b.y;
            ((float4*)sh[w][buf])[lane] = B;
        }
        const int nn = n + 1;
        if (j + 1 < NPW && nn < N_NODES) {
            if (lane < FEAT4) A = __ldg(&aggh2[nn * FEAT4 + lane]);
            dn = __ldg(&g_dinv[nn]);
        }
        __syncwarp();

        float hacc = 0.f;
        #pragma unroll
        for (int q = 0; q < 3; q++) {             // t-quads: t = 4q..4q+3
            unsigned long long uz0 = bzd_, uz1 = bzd_;
            unsigned long long uh0 = bhd_, uh1 = bhd_;
            #pragma unroll
            for (int f = 0; f < F_IN; f++) {
                ulonglong2 xa = *(const ulonglong2*)&sh[w][buf][f * T_P + q * 4];
                uz0 = fma2(xa.x, wzd[f], uz0);
                uz1 = fma2(xa.y, wzd[f], uz1);
                uh0 = fma2(xa.x, whd[f], uh0);
                uh1 = fma2(xa.y, whd[f], uh1);
            }
            uz0 = mul2(uz0, hfd_);                // 0.5 * uz (sigmoid-as-tanh)
            uz1 = mul2(uz1, hfd_);
            float z0, z1, z2, z3, h0, h1, h2, h3;
            unpack2(uz0, z0, z1); unpack2(uz1, z2, z3);
            unpack2(uh0, h0, h1); unpack2(uh1, h2, h3);
            // (1 - sigmoid(u)) = 0.5 - 0.5*tanh(u/2)
            float o0 = fmaf(-0.5f, fast_tanh(z0), 0.5f);
            float o1 = fmaf(-0.5f, fast_tanh(z1), 0.5f);
            float o2 = fmaf(-0.5f, fast_tanh(z2), 0.5f);
            float o3 = fmaf(-0.5f, fast_tanh(z3), 0.5f);
            hacc = fmaf(sProbs[q * 4 + 0], o0 * fast_tanh(h0), hacc);
            hacc = fmaf(sProbs[q * 4 + 1], o1 * fast_tanh(h1), hacc);
            hacc = fmaf(sProbs[q * 4 + 2], o2 * fast_tanh(h2), hacc);
            hacc = fmaf(sProbs[q * 4 + 3], o3 * fast_tanh(h3), hacc);
        }

        __syncwarp();
        sh[w][buf][lane] = fmaxf(hacc, 0.f);      // relu(H_accum)
        __syncwarp();

        if (lane < T_P) {
            float acc = sBout[lane];
            #pragma unroll
            for (int h = 0; h < HID; h++)
                acc = fmaf(sh[w][buf][h], sWout[h * T_P + lane], acc);
            out[n * T_P + lane] = acc;
        }
        __syncwarp();
    }
}

// ---------------- launch ----------------
extern "C" void kernel_launch(void* const* d_in, const int* in_sizes, int n_in,
                              void* d_out, int out_size) {
    const float* x    = (const float*)d_in[0];   // (N, F_IN, T)
    const int*   ei   = (const int*)  d_in[1];   // (2, E)
    const float* Wz   = (const float*)d_in[2];
    const float* bz   = (const float*)d_in[3];
    // d_in[4], d_in[5]: Wr, br  (dead: H0 == 0)
    const float* Wh   = (const float*)d_in[6];
    const float* bh   = (const float*)d_in[7];
    const float* Lz   = (const float*)d_in[8];
    const float* lz   = (const float*)d_in[9];
    // d_in[10], d_in[11]: Lr, lr (dead)
    const float* Lh   = (const float*)d_in[12];
    const float* lh   = (const float*)d_in[13];
    const float* att  = (const float*)d_in[14];
    const float* Wout = (const float*)d_in[15];
    const float* bout = (const float*)d_in[16];
    float* out = (float*)d_out;

    int E = in_sizes[1] / 2;
    const int* src = ei;
    const int* dst = ei + E;

    int E4 = E / 4;
    k_count_pre<<<(E4 + 255) / 256, 256>>>((const int4*)dst, E4,
                                           Wz, bz, Wh, bh, Lz, lz, Lh, lh, att);

    // Dependent kernels launch with programmatic stream serialization so their
    // launch latency overlaps the predecessor's tail; griddepcontrol.wait in
    // each kernel enforces the data dependency.
    cudaLaunchAttribute attr[1];
    attr[0].id = cudaLaunchAttributeProgrammaticStreamSerialization;
    attr[0].val.programmaticStreamSerializationAllowed = 1;

    {
        cudaLaunchConfig_t cfg = {};
        cfg.gridDim  = dim3((N_NODES * FEAT4 + 255) / 256);
        cfg.blockDim = dim3(256);
        cfg.attrs = attr;
        cfg.numAttrs = 1;
        cudaLaunchKernelEx(&cfg, k_mid, (const float4*)x);
    }
    {
        cudaLaunchConfig_t cfg = {};
        cfg.gridDim  = dim3((E * 4 + 255) / 256);
        cfg.blockDim = dim3(256);
        cfg.attrs = attr;
        cfg.numAttrs = 1;
        cudaLaunchKernelEx(&cfg, k_scatter, src, dst, E);
    }
    {
        int warps  = (N_NODES + NPW - 1) / NPW;  // 5000
        int blocks = (warps + 7) / 8;            // 625
        cudaLaunchConfig_t cfg = {};
        cfg.gridDim  = dim3(blocks);
        cfg.blockDim = dim3(256);
        cfg.attrs = attr;
        cfg.numAttrs = 1;
        cudaLaunchKernelEx(&cfg, k_node, (const float*)Wout, (const float*)bout, out);
    }
}

// round 13
// speedup vs baseline: 1.0082x; 1.0082x over previous
#include <cuda_runtime.h>
#include <cuda_fp16.h>

// Problem constants (fixed shapes for this problem)
#define N_NODES 20000
#define F_IN    8
#define T_P     12
#define HID     32
#define FEAT    96      // F_IN * T_P values per node
#define FEAT4   24      // FEAT / 4
#define NPW     4       // nodes per warp in k_node (two interleaved pairs)

// ---------------- device scratch (no allocations allowed) ----------------
// g_cnt starts zero (BSS) and is re-zeroed by k_node at the end of every run,
// so the pipeline is self-restoring across graph replays (no memset node).
__device__ float  g_cnt [N_NODES];               // edge in-degree
__device__ float  g_dinv[N_NODES];               // rsqrt(cnt + 1)
__device__ __align__(16) __half g_aggh[N_NODES * FEAT];  // fp16 accumulator
__device__ __align__(16) __half g_xh  [N_NODES * FEAT];  // fp16(dinv_n * x_n)
__device__ float  g_WLz [F_IN * HID];            // Wz @ Lz_top  (8 x 32)
__device__ float  g_WLh [F_IN * HID];            // Wh @ Lh_top  (8 x 32)
__device__ float  g_blz [HID];                   // bz @ Lz_top + lz
__device__ float  g_blh [HID];                   // bh @ Lh_top + lh
__device__ float  g_probs[T_P];                  // softmax(att)

__device__ __forceinline__ float fast_tanh(float x) {
    float y;
    asm("tanh.approx.f32 %0, %1;" : "=f"(y) : "f"(x));
    return y;
}

// ---- PDL (programmatic dependent launch) controls, sm_90+ ----
__device__ __forceinline__ void pdl_wait() {
    asm volatile("griddepcontrol.wait;" ::: "memory");
}
__device__ __forceinline__ void pdl_launch_dependents() {
    asm volatile("griddepcontrol.launch_dependents;" ::: "memory");
}

// ---- packed f32x2 helpers (Blackwell; exact fp32, 1 instr = 2 FMAs) ----
__device__ __forceinline__ unsigned long long pack2(float a, float b) {
    unsigned long long r;
    asm("mov.b64 %0, {%1, %2};" : "=l"(r) : "f"(a), "f"(b));
    return r;
}
__device__ __forceinline__ void unpack2(unsigned long long v, float& a, float& b) {
    asm("mov.b64 {%0, %1}, %2;" : "=f"(a), "=f"(b) : "l"(v));
}
__device__ __forceinline__ unsigned long long fma2(unsigned long long a,
                                                   unsigned long long b,
                                                   unsigned long long c) {
    unsigned long long r;
    asm("fma.rn.f32x2 %0, %1, %2, %3;" : "=l"(r) : "l"(a), "l"(b), "l"(c));
    return r;
}
__device__ __forceinline__ unsigned long long mul2(unsigned long long a,
                                                   unsigned long long b) {
    unsigned long long r;
    asm("mul.rn.f32x2 %0, %1, %2;" : "=l"(r) : "l"(a), "l"(b));
    return r;
}

// ---------------- kernels ----------------

// Degree histogram (4 edges/thread). Block 0 additionally folds the gate
// weights (WL = W @ L_top, bl = b @ L_top + l) and computes softmax(att).
__global__ void k_count_pre(const int4* __restrict__ dst4, int E4,
                            const float* __restrict__ Wz, const float* __restrict__ bz,
                            const float* __restrict__ Wh, const float* __restrict__ bh,
                            const float* __restrict__ Lz, const float* __restrict__ lz,
                            const float* __restrict__ Lh, const float* __restrict__ lh,
                            const float* __restrict__ att) {
    int i = blockIdx.x * blockDim.x + threadIdx.x;
    if (i < E4) {
        int4 d = __ldg(&dst4[i]);
        atomicAdd(&g_cnt[d.x], 1.0f);
        atomicAdd(&g_cnt[d.y], 1.0f);
        atomicAdd(&g_cnt[d.z], 1.0f);
        atomicAdd(&g_cnt[d.w], 1.0f);
    }
    if (blockIdx.x == 0) {
        int tid = threadIdx.x;
        if (tid < F_IN * HID) {
            int f = tid >> 5, h = tid & 31;
            float az = 0.f, ah = 0.f;
            #pragma unroll 8
            for (int k = 0; k < HID; k++) {
                az = fmaf(Wz[f * HID + k], Lz[k * HID + h], az);
                ah = fmaf(Wh[f * HID + k], Lh[k * HID + h], ah);
            }
            g_WLz[tid] = az;
            g_WLh[tid] = ah;
        }
        if (tid < HID) {
            float az = lz[tid], ah = lh[tid];
            for (int k = 0; k < HID; k++) {
                az = fmaf(bz[k], Lz[k * HID + tid], az);
                ah = fmaf(bh[k], Lh[k * HID + tid], ah);
            }
            g_blz[tid] = az;
            g_blh[tid] = ah;
        }
        if (tid == 0) {
            float m = -1e30f;
            for (int t = 0; t < T_P; t++) m = fmaxf(m, att[t]);
            float e[T_P], s = 0.f;
            for (int t = 0; t < T_P; t++) { e[t] = __expf(att[t] - m); s += e[t]; }
            float inv = 1.0f / s;
            for (int t = 0; t < T_P; t++) g_probs[t] = e[t] * inv;
        }
    }
    pdl_launch_dependents();                      // all of this block's writes done
}

// Node-indexed mid pass: dinv, fp16 pre-scaled features (xh), and seed the
// fp16 accumulator with the self-loop term. One thread per 4-value chunk.
__global__ void k_mid(const float4* __restrict__ x4) {
    pdl_wait();                                   // g_cnt must be complete
    int i = blockIdx.x * blockDim.x + threadIdx.x;
    if (i < N_NODES * FEAT4) {
        int n = i / FEAT4;
        float dn = rsqrtf(__ldg(&g_cnt[n]) + 1.0f);
        if ((i - n * FEAT4) == 0) g_dinv[n] = dn;
        float4 v = __ldg(&x4[i]);
        uint2 hv;
        *(__half2*)&hv.x = __floats2half2_rn(dn * v.x, dn * v.y);
        *(__half2*)&hv.y = __floats2half2_rn(dn * v.z, dn * v.w);
        ((uint2*)g_xh)[i]   = hv;
        ((uint2*)g_aggh)[i] = hv;                 // self-loop seed
    }
    pdl_launch_dependents();
}

// Scatter: aggh[dst] += xh[src]  (both fp16; vector f16x2 reductions).
// 4 threads per edge; lane owns 16B chunks sub, sub+4, sub+8.
__global__ void k_scatter(const int* __restrict__ src,
                          const int* __restrict__ dst, int E) {
    pdl_wait();                                   // xh/aggh seed must be complete
    int i = blockIdx.x * blockDim.x + threadIdx.x;
    int e = i >> 2;
    if (e < E) {
        int sub = i & 3;
        int s = __ldg(&src[e]);
        int d = __ldg(&dst[e]);

        const uint4* xs = (const uint4*)g_xh + s * 12;   // 12 x 16B = 96 halves
        uint4* ad = (uint4*)g_aggh + d * 12;
        #pragma unroll
        for (int k = 0; k < 3; k++) {
            int c = sub + k * 4;                  // 16B-chunk index 0..11
            uint4 v = __ldg(&xs[c]);
            asm volatile("red.global.add.noftz.v4.f16x2 [%0], {%1, %2, %3, %4};"
                         :: "l"(&ad[c]), "r"(v.x), "r"(v.y), "r"(v.z), "r"(v.w)
                         : "memory");
        }
    }
    pdl_launch_dependents();
}

// One warp handles NPW nodes as TWO INTERLEAVED PAIRS: two independent
// dependency chains per warp fill each other's stall slots. Output
// projection split across half-warps. Also re-zeroes g_cnt for next replay.
__global__ void __launch_bounds__(256)
k_node(const float* __restrict__ Wout,
       const float* __restrict__ bout,
       float* __restrict__ out) {
    __shared__ __align__(16) float sh[8][2][FEAT];   // per-warp: node A / node B
    __shared__ float sWout[HID * T_P];
    __shared__ float sBout[T_P];
    __shared__ float sProbs[T_P];

    const int tid  = threadIdx.x;
    const int w    = tid >> 5;
    const int lane = tid & 31;

    pdl_wait();                                   // aggh reductions complete

    // Reset the degree histogram for the next replay (self-restoring graph).
    {
        int gi = blockIdx.x * 256 + tid;
        if (gi < N_NODES) g_cnt[gi] = 0.0f;
    }

    for (int i = tid; i < HID * T_P; i += 256) sWout[i] = Wout[i];
    if (tid < T_P) { sBout[tid] = bout[tid]; sProbs[tid] = g_probs[tid]; }
    __syncthreads();

    // Packed gate weights (lane == hidden index h), duplicated into f32x2.
    unsigned long long wzd[F_IN], whd[F_IN];
    #pragma unroll
    for (int f = 0; f < F_IN; f++) {
        float a = __ldg(&g_WLz[f * HID + lane]);
        float b = __ldg(&g_WLh[f * HID + lane]);
        wzd[f] = pack2(a, a);
        whd[f] = pack2(b, b);
    }
    const float bz0 = __ldg(&g_blz[lane]);
    const float bh0 = __ldg(&g_blh[lane]);
    const unsigned long long bzd_ = pack2(bz0, bz0);
    const unsigned long long bhd_ = pack2(bh0, bh0);
    const unsigned long long hfd_ = pack2(0.5f, 0.5f);

    const int gwarp = blockIdx.x * 8 + w;
    const int base  = gwarp * NPW;                // N_NODES % NPW == 0: no tails
    const uint2* aggh2 = (const uint2*)g_aggh;    // 24 x 8B chunks per node

    #pragma unroll
    for (int jj = 0; jj < NPW; jj += 2) {
        const int n0 = base + jj;
        const int n1 = n0 + 1;

        // Load + scale both nodes' fp16 chunks into smem (lane<24: one chunk each).
        const float dn0 = __ldg(&g_dinv[n0]);
        const float dn1 = __ldg(&g_dinv[n1]);
        if (lane < FEAT4) {
            uint2 A0 = __ldg(&aggh2[n0 * FEAT4 + lane]);
            uint2 A1 = __ldg(&aggh2[n1 * FEAT4 + lane]);
            float2 a0 = __half22float2(*(const __half2*)&A0.x);
            float2 b0 = __half22float2(*(const __half2*)&A0.y);
            float2 a1 = __half22float2(*(const __half2*)&A1.x);
            float2 b1 = __half22float2(*(const __half2*)&A1.y);
            float4 B0, B1;
            B0.x = dn0 * a0.x; B0.y = dn0 * a0.y; B0.z = dn0 * b0.x; B0.w = dn0 * b0.y;
            B1.x = dn1 * a1.x; B1.y = dn1 * a1.y; B1.z = dn1 * b1.x; B1.w = dn1 * b1.y;
            ((float4*)sh[w][0])[lane] = B0;
            ((float4*)sh[w][1])[lane] = B1;
        }
        __syncwarp();

        float hacc0 = 0.f, hacc1 = 0.f;
        #pragma unroll
        for (int q = 0; q < 3; q++) {             // t-quads: t = 4q..4q+3
            unsigned long long za0 = bzd_, za1 = bzd_, ha0 = bhd_, ha1 = bhd_;
            unsigned long long zb0 = bzd_, zb1 = bzd_, hb0 = bhd_, hb1 = bhd_;
            #pragma unroll
            for (int f = 0; f < F_IN; f++) {
                ulonglong2 xa = *(const ulonglong2*)&sh[w][0][f * T_P + q * 4];
                ulonglong2 xb = *(const ulonglong2*)&sh[w][1][f * T_P + q * 4];
                za0 = fma2(xa.x, wzd[f], za0);
                zb0 = fma2(xb.x, wzd[f], zb0);
                za1 = fma2(xa.y, wzd[f], za1);
                zb1 = fma2(xb.y, wzd[f], zb1);
                ha0 = fma2(xa.x, whd[f], ha0);
                hb0 = fma2(xb.x, whd[f], hb0);
                ha1 = fma2(xa.y, whd[f], ha1);
                hb1 = fma2(xb.y, whd[f], hb1);
            }
            za0 = mul2(za0, hfd_); zb0 = mul2(zb0, hfd_);   // 0.5*uz for sigmoid
            za1 = mul2(za1, hfd_); zb1 = mul2(zb1, hfd_);
            float az0, az1, az2, az3, ah0, ah1, ah2, ah3;
            float bz0v, bz1v, bz2v, bz3v, bh0v, bh1v, bh2v, bh3v;
            unpack2(za0, az0, az1); unpack2(za1, az2, az3);
            unpack2(ha0, ah0, ah1); unpack2(ha1, ah2, ah3);
            unpack2(zb0, bz0v, bz1v); unpack2(zb1, bz2v, bz3v);
            unpack2(hb0, bh0v, bh1v); unpack2(hb1, bh2v, bh3v);
            // (1 - sigmoid(u)) = 0.5 - 0.5*tanh(u/2); interleave A/B tanh streams
            float oa0 = fmaf(-0.5f, fast_tanh(az0), 0.5f);
            float ob0 = fmaf(-0.5f, fast_tanh(bz0v), 0.5f);
            float oa1 = fmaf(-0.5f, fast_tanh(az1), 0.5f);
            float ob1 = fmaf(-0.5f, fast_tanh(bz1v), 0.5f);
            float oa2 = fmaf(-0.5f, fast_tanh(az2), 0.5f);
            float ob2 = fmaf(-0.5f, fast_tanh(bz2v), 0.5f);
            float oa3 = fmaf(-0.5f, fast_tanh(az3), 0.5f);
            float ob3 = fmaf(-0.5f, fast_tanh(bz3v), 0.5f);
            hacc0 = fmaf(sProbs[q * 4 + 0], oa0 * fast_tanh(ah0), hacc0);
            hacc1 = fmaf(sProbs[q * 4 + 0], ob0 * fast_tanh(bh0v), hacc1);
            hacc0 = fmaf(sProbs[q * 4 + 1], oa1 * fast_tanh(ah1), hacc0);
            hacc1 = fmaf(sProbs[q * 4 + 1], ob1 * fast_tanh(bh1v), hacc1);
            hacc0 = fmaf(sProbs[q * 4 + 2], oa2 * fast_tanh(ah2), hacc0);
            hacc1 = fmaf(sProbs[q * 4 + 2], ob2 * fast_tanh(bh2v), hacc1);
            hacc0 = fmaf(sProbs[q * 4 + 3], oa3 * fast_tanh(ah3), hacc0);
            hacc1 = fmaf(sProbs[q * 4 + 3], ob3 * fast_tanh(bh3v), hacc1);
        }

        __syncwarp();
        sh[w][0][lane] = fmaxf(hacc0, 0.f);       // relu(H_accum), node A
        sh[w][1][lane] = fmaxf(hacc1, 0.f);       // node B
        __syncwarp();

        // Output projection: half-warp per node (lanes 0-11 -> A, 16-27 -> B).
        const int sel = lane >> 4;                // 0: node A, 1: node B
        const int tl  = lane & 15;
        if (tl < T_P) {
            float acc = sBout[tl];
            #pragma unroll
            for (int h = 0; h < HID; h++)
                acc = fmaf(sh[w][sel][h], sWout[h * T_P + tl], acc);
            out[(sel ? n1 : n0) * T_P + tl] = acc;
        }
        __syncwarp();
    }
}

// ---------------- launch ----------------
extern "C" void kernel_launch(void* const* d_in, const int* in_sizes, int n_in,
                              void* d_out, int out_size) {
    const float* x    = (const float*)d_in[0];   // (N, F_IN, T)
    const int*   ei   = (const int*)  d_in[1];   // (2, E)
    const float* Wz   = (const float*)d_in[2];
    const float* bz   = (const float*)d_in[3];
    // d_in[4], d_in[5]: Wr, br  (dead: H0 == 0)
    const float* Wh   = (const float*)d_in[6];
    const float* bh   = (const float*)d_in[7];
    const float* Lz   = (const float*)d_in[8];
    const float* lz   = (const float*)d_in[9];
    // d_in[10], d_in[11]: Lr, lr (dead)
    const float* Lh   = (const float*)d_in[12];
    const float* lh   = (const float*)d_in[13];
    const float* att  = (const float*)d_in[14];
    const float* Wout = (const float*)d_in[15];
    const float* bout = (const float*)d_in[16];
    float* out = (float*)d_out;

    int E = in_sizes[1] / 2;
    const int* src = ei;
    const int* dst = ei + E;

    int E4 = E / 4;
    k_count_pre<<<(E4 + 255) / 256, 256>>>((const int4*)dst, E4,
                                           Wz, bz, Wh, bh, Lz, lz, Lh, lh, att);

    // Dependent kernels launch with programmatic stream serialization so their
    // launch latency overlaps the predecessor's tail; griddepcontrol.wait in
    // each kernel enforces the data dependency.
    cudaLaunchAttribute attr[1];
    attr[0].id = cudaLaunchAttributeProgrammaticStreamSerialization;
    attr[0].val.programmaticStreamSerializationAllowed = 1;

    {
        cudaLaunchConfig_t cfg = {};
        cfg.gridDim  = dim3((N_NODES * FEAT4 + 255) / 256);
        cfg.blockDim = dim3(256);
        cfg.attrs = attr;
        cfg.numAttrs = 1;
        cudaLaunchKernelEx(&cfg, k_mid, (const float4*)x);
    }
    {
        cudaLaunchConfig_t cfg = {};
        cfg.gridDim  = dim3((E * 4 + 255) / 256);
        cfg.blockDim = dim3(256);
        cfg.attrs = attr;
        cfg.numAttrs = 1;
        cudaLaunchKernelEx(&cfg, k_scatter, src, dst, E);
    }
    {
        int warps  = (N_NODES + NPW - 1) / NPW;  // 5000
        int blocks = (warps + 7) / 8;            // 625
        cudaLaunchConfig_t cfg = {};
        cfg.gridDim  = dim3(blocks);
        cfg.blockDim = dim3(256);
        cfg.attrs = attr;
        cfg.numAttrs = 1;
        cudaLaunchKernelEx(&cfg, k_node, (const float*)Wout, (const float*)bout, out);
    }
}

// round 14
// speedup vs baseline: 1.0503x; 1.0418x over previous
#include <cuda_runtime.h>
#include <cuda_fp16.h>

// Problem constants (fixed shapes for this problem)
#define N_NODES 20000
#define F_IN    8
#define T_P     12
#define HID     32
#define FEAT    96      // F_IN * T_P values per node
#define FEAT4   24      // FEAT / 4

// ---------------- device scratch (no allocations allowed) ----------------
// g_cnt starts zero (BSS) and is re-zeroed by k_node at the end of every run,
// so the pipeline is self-restoring across graph replays (no memset node).
__device__ float  g_cnt [N_NODES];               // edge in-degree
__device__ float  g_dinv[N_NODES];               // rsqrt(cnt + 1)
__device__ __align__(16) __half g_aggh[N_NODES * FEAT];  // fp16 accumulator
__device__ __align__(16) __half g_xh  [N_NODES * FEAT];  // fp16(dinv_n * x_n)
__device__ float  g_WLz [F_IN * HID];            // Wz @ Lz_top  (8 x 32)
__device__ float  g_WLh [F_IN * HID];            // Wh @ Lh_top  (8 x 32)
__device__ float  g_blz [HID];                   // bz @ Lz_top + lz
__device__ float  g_blh [HID];                   // bh @ Lh_top + lh
__device__ float  g_probs[T_P];                  // softmax(att)

__device__ __forceinline__ float fast_tanh(float x) {
    float y;
    asm("tanh.approx.f32 %0, %1;" : "=f"(y) : "f"(x));
    return y;
}

// ---- PDL (programmatic dependent launch) controls, sm_90+ ----
__device__ __forceinline__ void pdl_wait() {
    asm volatile("griddepcontrol.wait;" ::: "memory");
}
__device__ __forceinline__ void pdl_launch_dependents() {
    asm volatile("griddepcontrol.launch_dependents;" ::: "memory");
}

// ---- packed f32x2 helpers (Blackwell; exact fp32, 1 instr = 2 FMAs) ----
__device__ __forceinline__ unsigned long long pack2(float a, float b) {
    unsigned long long r;
    asm("mov.b64 %0, {%1, %2};" : "=l"(r) : "f"(a), "f"(b));
    return r;
}
__device__ __forceinline__ void unpack2(unsigned long long v, float& a, float& b) {
    asm("mov.b64 {%0, %1}, %2;" : "=f"(a), "=f"(b) : "l"(v));
}
__device__ __forceinline__ unsigned long long fma2(unsigned long long a,
                                                   unsigned long long b,
                                                   unsigned long long c) {
    unsigned long long r;
    asm("fma.rn.f32x2 %0, %1, %2, %3;" : "=l"(r) : "l"(a), "l"(b), "l"(c));
    return r;
}
__device__ __forceinline__ unsigned long long mul2(unsigned long long a,
                                                   unsigned long long b) {
    unsigned long long r;
    asm("mul.rn.f32x2 %0, %1, %2;" : "=l"(r) : "l"(a), "l"(b));
    return r;
}

// ---------------- kernels ----------------

// Degree histogram (4 edges/thread). Block 0 additionally folds the gate
// weights (WL = W @ L_top, bl = b @ L_top + l) and computes softmax(att).
__global__ void k_count_pre(const int4* __restrict__ dst4, int E4,
                            const float* __restrict__ Wz, const float* __restrict__ bz,
                            const float* __restrict__ Wh, const float* __restrict__ bh,
                            const float* __restrict__ Lz, const float* __restrict__ lz,
                            const float* __restrict__ Lh, const float* __restrict__ lh,
                            const float* __restrict__ att) {
    int i = blockIdx.x * blockDim.x + threadIdx.x;
    if (i < E4) {
        int4 d = __ldg(&dst4[i]);
        atomicAdd(&g_cnt[d.x], 1.0f);
        atomicAdd(&g_cnt[d.y], 1.0f);
        atomicAdd(&g_cnt[d.z], 1.0f);
        atomicAdd(&g_cnt[d.w], 1.0f);
    }
    if (blockIdx.x == 0) {
        int tid = threadIdx.x;
        if (tid < F_IN * HID) {
            int f = tid >> 5, h = tid & 31;
            float az = 0.f, ah = 0.f;
            #pragma unroll 8
            for (int k = 0; k < HID; k++) {
                az = fmaf(Wz[f * HID + k], Lz[k * HID + h], az);
                ah = fmaf(Wh[f * HID + k], Lh[k * HID + h], ah);
            }
            g_WLz[tid] = az;
            g_WLh[tid] = ah;
        }
        if (tid < HID) {
            float az = lz[tid], ah = lh[tid];
            for (int k = 0; k < HID; k++) {
                az = fmaf(bz[k], Lz[k * HID + tid], az);
                ah = fmaf(bh[k], Lh[k * HID + tid], ah);
            }
            g_blz[tid] = az;
            g_blh[tid] = ah;
        }
        if (tid == 0) {
            float m = -1e30f;
            for (int t = 0; t < T_P; t++) m = fmaxf(m, att[t]);
            float e[T_P], s = 0.f;
            for (int t = 0; t < T_P; t++) { e[t] = __expf(att[t] - m); s += e[t]; }
            float inv = 1.0f / s;
            for (int t = 0; t < T_P; t++) g_probs[t] = e[t] * inv;
        }
    }
    pdl_launch_dependents();                      // all of this block's writes done
}

// Node-indexed mid pass: dinv, fp16 pre-scaled features (xh), and seed the
// fp16 accumulator with the self-loop term. One thread per 4-value chunk.
__global__ void k_mid(const float4* __restrict__ x4) {
    pdl_wait();                                   // g_cnt must be complete
    int i = blockIdx.x * blockDim.x + threadIdx.x;
    if (i < N_NODES * FEAT4) {
        int n = i / FEAT4;
        float dn = rsqrtf(__ldg(&g_cnt[n]) + 1.0f);
        if ((i - n * FEAT4) == 0) g_dinv[n] = dn;
        float4 v = __ldg(&x4[i]);
        uint2 hv;
        *(__half2*)&hv.x = __floats2half2_rn(dn * v.x, dn * v.y);
        *(__half2*)&hv.y = __floats2half2_rn(dn * v.z, dn * v.w);
        ((uint2*)g_xh)[i]   = hv;
        ((uint2*)g_aggh)[i] = hv;                 // self-loop seed
    }
    pdl_launch_dependents();
}

// Scatter: aggh[dst] += xh[src]  (both fp16; vector f16x2 reductions).
// 4 threads per edge; lane owns 16B chunks sub, sub+4, sub+8.
__global__ void k_scatter(const int* __restrict__ src,
                          const int* __restrict__ dst, int E) {
    pdl_wait();                                   // xh/aggh seed must be complete
    int i = blockIdx.x * blockDim.x + threadIdx.x;
    int e = i >> 2;
    if (e < E) {
        int sub = i & 3;
        int s = __ldg(&src[e]);
        int d = __ldg(&dst[e]);

        const uint4* xs = (const uint4*)g_xh + s * 12;   // 12 x 16B = 96 halves
        uint4* ad = (uint4*)g_aggh + d * 12;
        #pragma unroll
        for (int k = 0; k < 3; k++) {
            int c = sub + k * 4;                  // 16B-chunk index 0..11
            uint4 v = __ldg(&xs[c]);
            asm volatile("red.global.add.noftz.v4.f16x2 [%0], {%1, %2, %3, %4};"
                         :: "l"(&ad[c]), "r"(v.x), "r"(v.y), "r"(v.z), "r"(v.w)
                         : "memory");
        }
    }
    pdl_launch_dependents();
}

// One warp handles exactly TWO nodes as interleaved dependency chains
// (grid 1250 blocks -> machine stays full). Output projection split across
// half-warps. Also re-zeroes g_cnt for the next graph replay.
__global__ void __launch_bounds__(256)
k_node(const float* __restrict__ Wout,
       const float* __restrict__ bout,
       float* __restrict__ out) {
    __shared__ __align__(16) float sh[8][2][FEAT];   // per-warp: node A / node B
    __shared__ float sWout[HID * T_P];
    __shared__ float sBout[T_P];
    __shared__ float sProbs[T_P];

    const int tid  = threadIdx.x;
    const int w    = tid >> 5;
    const int lane = tid & 31;

    pdl_wait();                                   // aggh reductions complete

    // Reset the degree histogram for the next replay (self-restoring graph).
    {
        int gi = blockIdx.x * 16 + (tid >> 4);    // 1250 blocks x 16 = 20000
        if (gi < N_NODES && (tid & 15) == 0) g_cnt[gi] = 0.0f;
    }

    for (int i = tid; i < HID * T_P; i += 256) sWout[i] = Wout[i];
    if (tid < T_P) { sBout[tid] = bout[tid]; sProbs[tid] = g_probs[tid]; }
    __syncthreads();

    // Packed gate weights (lane == hidden index h), duplicated into f32x2.
    unsigned long long wzd[F_IN], whd[F_IN];
    #pragma unroll
    for (int f = 0; f < F_IN; f++) {
        float a = __ldg(&g_WLz[f * HID + lane]);
        float b = __ldg(&g_WLh[f * HID + lane]);
        wzd[f] = pack2(a, a);
        whd[f] = pack2(b, b);
    }
    const float bz0 = __ldg(&g_blz[lane]);
    const float bh0 = __ldg(&g_blh[lane]);
    const unsigned long long bzd_ = pack2(bz0, bz0);
    const unsigned long long bhd_ = pack2(bh0, bh0);
    const unsigned long long hfd_ = pack2(0.5f, 0.5f);

    const int gwarp = blockIdx.x * 8 + w;
    const int n0 = gwarp * 2;                     // 10000 warps x 2 = 20000 nodes
    const int n1 = n0 + 1;
    const uint2* aggh2 = (const uint2*)g_aggh;    // 24 x 8B chunks per node

    // Load + scale both nodes' fp16 chunks into smem (lane<24: one chunk each).
    const float dn0 = __ldg(&g_dinv[n0]);
    const float dn1 = __ldg(&g_dinv[n1]);
    if (lane < FEAT4) {
        uint2 A0 = __ldg(&aggh2[n0 * FEAT4 + lane]);
        uint2 A1 = __ldg(&aggh2[n1 * FEAT4 + lane]);
        float2 a0 = __half22float2(*(const __half2*)&A0.x);
        float2 b0 = __half22float2(*(const __half2*)&A0.y);
        float2 a1 = __half22float2(*(const __half2*)&A1.x);
        float2 b1 = __half22float2(*(const __half2*)&A1.y);
        float4 B0, B1;
        B0.x = dn0 * a0.x; B0.y = dn0 * a0.y; B0.z = dn0 * b0.x; B0.w = dn0 * b0.y;
        B1.x = dn1 * a1.x; B1.y = dn1 * a1.y; B1.z = dn1 * b1.x; B1.w = dn1 * b1.y;
        ((float4*)sh[w][0])[lane] = B0;
        ((float4*)sh[w][1])[lane] = B1;
    }
    __syncwarp();

    float hacc0 = 0.f, hacc1 = 0.f;
    #pragma unroll
    for (int q = 0; q < 3; q++) {                 // t-quads: t = 4q..4q+3
        unsigned long long za0 = bzd_, za1 = bzd_, ha0 = bhd_, ha1 = bhd_;
        unsigned long long zb0 = bzd_, zb1 = bzd_, hb0 = bhd_, hb1 = bhd_;
        #pragma unroll
        for (int f = 0; f < F_IN; f++) {
            ulonglong2 xa = *(const ulonglong2*)&sh[w][0][f * T_P + q * 4];
            ulonglong2 xb = *(const ulonglong2*)&sh[w][1][f * T_P + q * 4];
            za0 = fma2(xa.x, wzd[f], za0);
            zb0 = fma2(xb.x, wzd[f], zb0);
            za1 = fma2(xa.y, wzd[f], za1);
            zb1 = fma2(xb.y, wzd[f], zb1);
            ha0 = fma2(xa.x, whd[f], ha0);
            hb0 = fma2(xb.x, whd[f], hb0);
            ha1 = fma2(xa.y, whd[f], ha1);
            hb1 = fma2(xb.y, whd[f], hb1);
        }
        za0 = mul2(za0, hfd_); zb0 = mul2(zb0, hfd_);       // 0.5*uz for sigmoid
        za1 = mul2(za1, hfd_); zb1 = mul2(zb1, hfd_);
        float az0, az1, az2, az3, ah0, ah1, ah2, ah3;
        float bz0v, bz1v, bz2v, bz3v, bh0v, bh1v, bh2v, bh3v;
        unpack2(za0, az0, az1); unpack2(za1, az2, az3);
        unpack2(ha0, ah0, ah1); unpack2(ha1, ah2, ah3);
        unpack2(zb0, bz0v, bz1v); unpack2(zb1, bz2v, bz3v);
        unpack2(hb0, bh0v, bh1v); unpack2(hb1, bh2v, bh3v);
        // (1 - sigmoid(u)) = 0.5 - 0.5*tanh(u/2); interleave A/B tanh streams
        float oa0 = fmaf(-0.5f, fast_tanh(az0), 0.5f);
        float ob0 = fmaf(-0.5f, fast_tanh(bz0v), 0.5f);
        float oa1 = fmaf(-0.5f, fast_tanh(az1), 0.5f);
        float ob1 = fmaf(-0.5f, fast_tanh(bz1v), 0.5f);
        float oa2 = fmaf(-0.5f, fast_tanh(az2), 0.5f);
        float ob2 = fmaf(-0.5f, fast_tanh(bz2v), 0.5f);
        float oa3 = fmaf(-0.5f, fast_tanh(az3), 0.5f);
        float ob3 = fmaf(-0.5f, fast_tanh(bz3v), 0.5f);
        hacc0 = fmaf(sProbs[q * 4 + 0], oa0 * fast_tanh(ah0), hacc0);
        hacc1 = fmaf(sProbs[q * 4 + 0], ob0 * fast_tanh(bh0v), hacc1);
        hacc0 = fmaf(sProbs[q * 4 + 1], oa1 * fast_tanh(ah1), hacc0);
        hacc1 = fmaf(sProbs[q * 4 + 1], ob1 * fast_tanh(bh1v), hacc1);
        hacc0 = fmaf(sProbs[q * 4 + 2], oa2 * fast_tanh(ah2), hacc0);
        hacc1 = fmaf(sProbs[q * 4 + 2], ob2 * fast_tanh(bh2v), hacc1);
        hacc0 = fmaf(sProbs[q * 4 + 3], oa3 * fast_tanh(ah3), hacc0);
        hacc1 = fmaf(sProbs[q * 4 + 3], ob3 * fast_tanh(bh3v), hacc1);
    }

    __syncwarp();
    sh[w][0][lane] = fmaxf(hacc0, 0.f);           // relu(H_accum), node A
    sh[w][1][lane] = fmaxf(hacc1, 0.f);           // node B
    __syncwarp();

    // Output projection: half-warp per node (lanes 0-11 -> A, 16-27 -> B).
    const int sel = lane >> 4;                    // 0: node A, 1: node B
    const int tl  = lane & 15;
    if (tl < T_P) {
        float acc = sBout[tl];
        #pragma unroll
        for (int h = 0; h < HID; h++)
            acc = fmaf(sh[w][sel][h], sWout[h * T_P + tl], acc);
        out[(sel ? n1 : n0) * T_P + tl] = acc;
    }
}

// ---------------- launch ----------------
extern "C" void kernel_launch(void* const* d_in, const int* in_sizes, int n_in,
                              void* d_out, int out_size) {
    const float* x    = (const float*)d_in[0];   // (N, F_IN, T)
    const int*   ei   = (const int*)  d_in[1];   // (2, E)
    const float* Wz   = (const float*)d_in[2];
    const float* bz   = (const float*)d_in[3];
    // d_in[4], d_in[5]: Wr, br  (dead: H0 == 0)
    const float* Wh   = (const float*)d_in[6];
    const float* bh   = (const float*)d_in[7];
    const float* Lz   = (const float*)d_in[8];
    const float* lz   = (const float*)d_in[9];
    // d_in[10], d_in[11]: Lr, lr (dead)
    const float* Lh   = (const float*)d_in[12];
    const float* lh   = (const float*)d_in[13];
    const float* att  = (const float*)d_in[14];
    const float* Wout = (const float*)d_in[15];
    const float* bout = (const float*)d_in[16];
    float* out = (float*)d_out;

    int E = in_sizes[1] / 2;
    const int* src = ei;
    const int* dst = ei + E;

    int E4 = E / 4;
    k_count_pre<<<(E4 + 255) / 256, 256>>>((const int4*)dst, E4,
                                           Wz, bz, Wh, bh, Lz, lz, Lh, lh, att);

    // Dependent kernels launch with programmatic stream serialization so their
    // launch latency overlaps the predecessor's tail; griddepcontrol.wait in
    // each kernel enforces the data dependency.
    cudaLaunchAttribute attr[1];
    attr[0].id = cudaLaunchAttributeProgrammaticStreamSerialization;
    attr[0].val.programmaticStreamSerializationAllowed = 1;

    {
        cudaLaunchConfig_t cfg = {};
        cfg.gridDim  = dim3((N_NODES * FEAT4 + 255) / 256);
        cfg.blockDim = dim3(256);
        cfg.attrs = attr;
        cfg.numAttrs = 1;
        cudaLaunchKernelEx(&cfg, k_mid, (const float4*)x);
    }
    {
        cudaLaunchConfig_t cfg = {};
        cfg.gridDim  = dim3((E * 4 + 255) / 256);
        cfg.blockDim = dim3(256);
        cfg.attrs = attr;
        cfg.numAttrs = 1;
        cudaLaunchKernelEx(&cfg, k_scatter, src, dst, E);
    }
    {
        int blocks = (N_NODES / 2 + 7) / 8;      // 1250 blocks, 1 pair per warp
        cudaLaunchConfig_t cfg = {};
        cfg.gridDim  = dim3(blocks);
        cfg.blockDim = dim3(256);
        cfg.attrs = attr;
        cfg.numAttrs = 1;
        cudaLaunchKernelEx(&cfg, k_node, (const float*)Wout, (const float*)bout, out);
    }
}